// round 6
// baseline (speedup 1.0000x reference)
#include <cuda_runtime.h>

#define BB   32
#define LL   4096
#define IN   1024
#define QSZ  64
#define VSZ  256
#define HH   16
#define NCHUNK 16          // k_att blocks per batch (l-chunks of 256)
#define LCH  256
#define NSLOT 64           // partial slots = NCHUNK * 4 (l-quarters)

// Scratch (__device__ globals; no allocation allowed)
__device__ float g_q[BB*IN];                     // 128 KB
__device__ float g_partial[BB*NSLOT*HH*VSZ];     // 32 MB
__device__ float g_s[BB*NSLOT*HH];               // per-slot expsum
__device__ float g_pv[BB*HH*VSZ];                // 512 KB

typedef unsigned long long u64;

__device__ __forceinline__ u64 pack2(float lo, float hi) {
    u64 r; asm("mov.b64 %0, {%1, %2};" : "=l"(r) : "f"(lo), "f"(hi)); return r;
}
__device__ __forceinline__ u64 fma2(u64 a, u64 b, u64 c) {
    u64 d; asm("fma.rn.f32x2 %0, %1, %2, %3;" : "=l"(d) : "l"(a), "l"(b), "l"(c)); return d;
}
__device__ __forceinline__ float2 unpack2(u64 v) {
    float2 f; asm("mov.b64 {%0, %1}, %2;" : "=f"(f.x), "=f"(f.y) : "l"(v)); return f;
}

// ============================================================
// K1: q[b,n] = query[b,:].Wq[n,:] + bq[n]
// ============================================================
__global__ void __launch_bounds__(256) k_q(const float* __restrict__ query,
                                           const float* __restrict__ Wq,
                                           const float* __restrict__ bq) {
    __shared__ float qsm[8 * IN];
    int tid = threadIdx.x, lane = tid & 31, warp = tid >> 5;
    int n  = blockIdx.x * 8 + warp;
    int b0 = blockIdx.y * 8;

    const float4* qg = (const float4*)(query + (size_t)b0 * IN);
    float4* qs4 = (float4*)qsm;
    for (int i = tid; i < 8 * IN / 4; i += 256) qs4[i] = __ldg(qg + i);
    __syncthreads();

    const float4* w4 = (const float4*)(Wq + (size_t)n * IN);
    float acc[8];
#pragma unroll
    for (int b = 0; b < 8; b++) acc[b] = 0.f;

#pragma unroll
    for (int it = 0; it < 8; it++) {
        int idx = it * 32 + lane;
        float4 w = __ldg(w4 + idx);
#pragma unroll
        for (int b = 0; b < 8; b++) {
            float4 q = qs4[b * (IN / 4) + idx];
            acc[b] += w.x * q.x + w.y * q.y + w.z * q.z + w.w * q.w;
        }
    }
#pragma unroll
    for (int b = 0; b < 8; b++) {
#pragma unroll
        for (int o = 16; o; o >>= 1) acc[b] += __shfl_xor_sync(0xffffffffu, acc[b], o);
    }
    if (lane == 0) {
        float bias = bq[n];
#pragma unroll
        for (int b = 0; b < 8; b++)
            g_q[(size_t)(b0 + b) * IN + n] = acc[b] + bias;
    }
}

// ============================================================
// K2: fused scores + exp + weighted value partial sum.
// Phase A: thread = one l (256), writes exp-weights ps[l][8] (swizzled).
// Phase B: thread = (d8 = t&31, hgroup = (t>>5)&1, lq = t>>6).
//   Owns d columns {4*d8..4*d8+3} and {128+4*d8..+3}, 8 h, 64 l.
//   Per l: 2 LDG.128 (coalesced) + 4 LDS.128 (broadcast) + 32 FFMA2.
// ============================================================
__global__ void __launch_bounds__(256, 2) k_att(const float* __restrict__ key,
                                                const float* __restrict__ value) {
    __shared__ u64  qs[HH * QSZ / 2];          // 4 KB
    __shared__ ulonglong2 ps[LCH][8];          // 32 KB
    __shared__ float wsum[256];                // 1 KB

    int b = blockIdx.y, c = blockIdx.x;
    int tid = threadIdx.x;

    const float2* qsrc = (const float2*)(g_q + (size_t)b * IN);
    for (int i = tid; i < HH * QSZ / 2; i += 256) {
        float2 v = qsrc[i];
        qs[i] = pack2(v.x, v.y);
    }
    __syncthreads();

    // ---- Phase A: scores + exp for l = c*256 + tid ----
    {
        const float4* k4 = (const float4*)(key + ((size_t)b * LL + (size_t)c * LCH + tid) * QSZ);
        u64 acc[HH];
#pragma unroll
        for (int h = 0; h < HH; h++) acc[h] = pack2(0.f, 0.f);
#pragma unroll 4
        for (int d4 = 0; d4 < QSZ / 4; d4++) {
            float4 kk = __ldg(k4 + d4);
            u64 ka = pack2(kk.x, kk.y);
            u64 kb = pack2(kk.z, kk.w);
#pragma unroll
            for (int h = 0; h < HH; h++) {
                acc[h] = fma2(ka, qs[h * 32 + 2 * d4],     acc[h]);
                acc[h] = fma2(kb, qs[h * 32 + 2 * d4 + 1], acc[h]);
            }
        }
#pragma unroll
        for (int hp = 0; hp < 8; hp++) {
            float2 f0 = unpack2(acc[2 * hp]);
            float2 f1 = unpack2(acc[2 * hp + 1]);
            float e0 = __expf((f0.x + f0.y) * 0.125f);
            float e1 = __expf((f1.x + f1.y) * 0.125f);
            int slot = (hp + tid) & 7;
            ulonglong2 w;
            w.x = pack2(e0, e0);
            w.y = pack2(e1, e1);
            ps[tid][slot] = w;
        }
    }
    __syncthreads();

    // ---- per-(h, l-quarter) expsum from smem ----
    {
        int h = tid & 15, q = (tid >> 4) & 3, chunk = tid >> 6;   // chunk 0..3
        int hp = h >> 1, sub = h & 1;
        float s = 0.f;
#pragma unroll
        for (int i = 0; i < 16; i++) {
            int l = q * 64 + chunk * 16 + i;
            const u64* row = (const u64*)&ps[l][0];
            int slot = (hp + l) & 7;
            float2 f = unpack2(row[slot * 2 + sub]);
            s += f.x;
        }
        wsum[tid] = s;
    }
    __syncthreads();
    if (tid < 64) {
        int h = tid & 15, q = tid >> 4;
        float S = 0.f;
#pragma unroll
        for (int chunk = 0; chunk < 4; chunk++)
            S += wsum[chunk * 64 + q * 16 + h];
        g_s[((size_t)b * NSLOT + (size_t)c * 4 + q) * HH + h] = S;
    }

    // ---- Phase B ----
    int d8 = tid & 31, hgroup = (tid >> 5) & 1, lq = tid >> 6;   // lq 0..3
    const float4* vb = (const float4*)(value +
        ((size_t)b * LL + (size_t)c * LCH + (size_t)lq * 64) * VSZ);

    u64 acc[8][4];                              // [h-local][d2-pair]
#pragma unroll
    for (int j = 0; j < 8; j++)
#pragma unroll
        for (int k = 0; k < 4; k++) acc[j][k] = pack2(0.f, 0.f);

#pragma unroll 2
    for (int i = 0; i < 64; i++) {
        int l = lq * 64 + i;
        float4 va = __ldg(vb + (size_t)i * (VSZ / 4) + d8);        // d 4*d8..+3
        float4 vc = __ldg(vb + (size_t)i * (VSZ / 4) + 32 + d8);   // d 128+4*d8..+3
        u64 v0 = pack2(va.x, va.y);
        u64 v1 = pack2(va.z, va.w);
        u64 v2 = pack2(vc.x, vc.y);
        u64 v3 = pack2(vc.z, vc.w);
#pragma unroll
        for (int j = 0; j < 4; j++) {
            int hp = hgroup * 4 + j;
            int slot = (hp + l) & 7;
            ulonglong2 pp = ps[l][slot];        // LDS.128 broadcast
            acc[2 * j][0]     = fma2(v0, pp.x, acc[2 * j][0]);
            acc[2 * j][1]     = fma2(v1, pp.x, acc[2 * j][1]);
            acc[2 * j][2]     = fma2(v2, pp.x, acc[2 * j][2]);
            acc[2 * j][3]     = fma2(v3, pp.x, acc[2 * j][3]);
            acc[2 * j + 1][0] = fma2(v0, pp.y, acc[2 * j + 1][0]);
            acc[2 * j + 1][1] = fma2(v1, pp.y, acc[2 * j + 1][1]);
            acc[2 * j + 1][2] = fma2(v2, pp.y, acc[2 * j + 1][2]);
            acc[2 * j + 1][3] = fma2(v3, pp.y, acc[2 * j + 1][3]);
        }
    }

    int slot_out = c * 4 + lq;
    float* base = g_partial + ((size_t)(b * NSLOT + slot_out) * HH + hgroup * 8) * VSZ;
#pragma unroll
    for (int j = 0; j < 8; j++) {
        float2 a0 = unpack2(acc[j][0]);
        float2 a1 = unpack2(acc[j][1]);
        float2 a2 = unpack2(acc[j][2]);
        float2 a3 = unpack2(acc[j][3]);
        float* row = base + (size_t)j * VSZ;
        *(float4*)(row + 4 * d8)       = make_float4(a0.x, a0.y, a1.x, a1.y);
        *(float4*)(row + 128 + 4 * d8) = make_float4(a2.x, a2.y, a3.x, a3.y);
    }
}

// ============================================================
// K3: combine 64 slots: sum partials, sum S, normalize.
// ============================================================
__global__ void __launch_bounds__(256) k_red() {
    int g = blockIdx.x * 256 + threadIdx.x;
    int d2 = g & 127;
    int h  = (g >> 7) & (HH - 1);
    int b  = g >> 11;

    const float* sp = g_s + (size_t)b * NSLOT * HH + h;
    float S = 0.f;
#pragma unroll 8
    for (int c = 0; c < NSLOT; c++) S += sp[c * HH];

    const float2* pp = (const float2*)(g_partial + ((size_t)b * NSLOT * HH + h) * VSZ) + d2;
    float2 pv = make_float2(0.f, 0.f);
#pragma unroll 8
    for (int c = 0; c < NSLOT; c++) {
        float2 v = pp[(size_t)c * HH * (VSZ / 2)];
        pv.x += v.x;
        pv.y += v.y;
    }
    float inv = 1.0f / S;
    ((float2*)(g_pv + (size_t)(b * HH + h) * VSZ))[d2] = make_float2(pv.x * inv, pv.y * inv);
}

// ============================================================
// K4: out[b,n] = Wv[n,:].pv[b, n>>6, :] + bv[n]
// ============================================================
__global__ void __launch_bounds__(256) k_out(const float* __restrict__ Wv,
                                             const float* __restrict__ bv,
                                             float* __restrict__ out) {
    __shared__ float pvs[8 * VSZ];
    int tid = threadIdx.x, lane = tid & 31, warp = tid >> 5;
    int n  = blockIdx.x * 8 + warp;
    int b0 = blockIdx.y * 8;
    int h  = (blockIdx.x * 8) >> 6;

    float4* pv4 = (float4*)pvs;
    for (int i = tid; i < 8 * VSZ / 4; i += 256) {
        int bl = i / (VSZ / 4), k4 = i % (VSZ / 4);
        pv4[i] = ((const float4*)(g_pv + (size_t)((b0 + bl) * HH + h) * VSZ))[k4];
    }
    __syncthreads();

    const float4* w4 = (const float4*)(Wv + (size_t)n * VSZ);
    float acc[8];
#pragma unroll
    for (int b = 0; b < 8; b++) acc[b] = 0.f;

#pragma unroll
    for (int it = 0; it < 2; it++) {
        int idx = it * 32 + lane;
        float4 w = __ldg(w4 + idx);
#pragma unroll
        for (int b = 0; b < 8; b++) {
            float4 p = pv4[b * (VSZ / 4) + idx];
            acc[b] += w.x * p.x + w.y * p.y + w.z * p.z + w.w * p.w;
        }
    }
#pragma unroll
    for (int b = 0; b < 8; b++) {
#pragma unroll
        for (int o = 16; o; o >>= 1) acc[b] += __shfl_xor_sync(0xffffffffu, acc[b], o);
    }
    if (lane == 0) {
        float bias = bv[n];
#pragma unroll
        for (int b = 0; b < 8; b++)
            out[(size_t)(b0 + b) * IN + n] = acc[b] + bias;
    }
}

// ============================================================
extern "C" void kernel_launch(void* const* d_in, const int* in_sizes, int n_in,
                              void* d_out, int out_size) {
    const float* query = (const float*)d_in[0];
    const float* key   = (const float*)d_in[1];
    const float* value = (const float*)d_in[2];
    const float* Wq    = (const float*)d_in[3];
    const float* bq    = (const float*)d_in[4];
    const float* Wv    = (const float*)d_in[5];
    const float* bv    = (const float*)d_in[6];
    float* out = (float*)d_out;

    k_q<<<dim3(IN / 8, BB / 8), 256>>>(query, Wq, bq);
    k_att<<<dim3(NCHUNK, BB), 256>>>(key, value);
    k_red<<<BB * HH * (VSZ / 2) / 256, 256>>>();
    k_out<<<dim3(IN / 8, BB / 8), 256>>>(Wv, bv, out);
}